// round 2
// baseline (speedup 1.0000x reference)
#include <cuda_runtime.h>
#include <math.h>

#define B_DIM 1024
#define D_DIM 512
#define C_DIM 51332

#define EPS_F   1e-3f
#define SCALE_F 64.0f

// scratch: inverse L2 norm of each kernel column (device global; no allocation)
__device__ float g_invnorm[C_DIM];

// ---------------------------------------------------------------------------
// Kernel 1: column norms of kernel [D, C] (row-major). Coalesced over c.
// ---------------------------------------------------------------------------
__global__ void colnorm_kernel(const float* __restrict__ kern) {
    int c = blockIdx.x * blockDim.x + threadIdx.x;
    if (c >= C_DIM) return;
    float sum = 0.0f;
#pragma unroll 8
    for (int d = 0; d < D_DIM; ++d) {
        float v = kern[d * C_DIM + c];
        sum = fmaf(v, v, sum);
    }
    float n = fmaxf(sqrtf(sum), 1e-5f);
    g_invnorm[c] = 1.0f / n;
}

// ---------------------------------------------------------------------------
// Kernel 2: tiled SGEMM with fused AdaFace epilogue for non-label columns.
// out[b,c] = S * clip( (emb[b,:] . kernel[:,c]) * invnorm[c], -1+eps, 1-eps )
// 128x128 tile, BK=8, 256 threads, 8x8 per-thread register tile.
// ---------------------------------------------------------------------------
#define BM 128
#define BN 128
#define BK 8
#define TM 8
#define TN 8

__global__ __launch_bounds__(256, 2)
void gemm_epilogue_kernel(const float* __restrict__ A,   // emb [B, D]
                          const float* __restrict__ Bm,  // kernel [D, C]
                          float* __restrict__ out)       // [B, C]
{
    __shared__ float As[BK][BM];
    __shared__ float Bs[BK][BN];

    const int tid  = threadIdx.x;
    const int trow = tid >> 4;       // 0..15
    const int tcol = tid & 15;       // 0..15

    const int rowBase = blockIdx.y * BM;
    const int colBase = blockIdx.x * BN;

    // A tile load indices: 128x8 floats, one float4 per thread
    const int aRow = tid >> 1;            // 0..127
    const int aCol = (tid & 1) * 4;       // 0 or 4
    // B tile load indices: 8x128 floats, one float4 per thread
    const int bRow = tid >> 5;            // 0..7
    const int bCol = (tid & 31) * 4;      // 0..124

    const float* Aptr = A + rowBase * D_DIM;

    float acc[TM][TN];
#pragma unroll
    for (int i = 0; i < TM; ++i)
#pragma unroll
        for (int j = 0; j < TN; ++j) acc[i][j] = 0.0f;

    for (int k0 = 0; k0 < D_DIM; k0 += BK) {
        // load A 128x8 (transpose into As[k][m])
        float4 av = *reinterpret_cast<const float4*>(Aptr + aRow * D_DIM + k0 + aCol);
        As[aCol + 0][aRow] = av.x;
        As[aCol + 1][aRow] = av.y;
        As[aCol + 2][aRow] = av.z;
        As[aCol + 3][aRow] = av.w;

        // load B 8x128 with column guard (C_DIM % 4 == 0 so float4-granular)
        int gcol = colBase + bCol;
        float4 bv = make_float4(0.f, 0.f, 0.f, 0.f);
        if (gcol < C_DIM)
            bv = *reinterpret_cast<const float4*>(Bm + (k0 + bRow) * C_DIM + gcol);
        *reinterpret_cast<float4*>(&Bs[bRow][bCol]) = bv;

        __syncthreads();

#pragma unroll
        for (int kk = 0; kk < BK; ++kk) {
            float a[TM], b[TN];
            float4 a0 = *reinterpret_cast<const float4*>(&As[kk][trow * TM]);
            float4 a1 = *reinterpret_cast<const float4*>(&As[kk][trow * TM + 4]);
            float4 b0 = *reinterpret_cast<const float4*>(&Bs[kk][tcol * TN]);
            float4 b1 = *reinterpret_cast<const float4*>(&Bs[kk][tcol * TN + 4]);
            a[0] = a0.x; a[1] = a0.y; a[2] = a0.z; a[3] = a0.w;
            a[4] = a1.x; a[5] = a1.y; a[6] = a1.z; a[7] = a1.w;
            b[0] = b0.x; b[1] = b0.y; b[2] = b0.z; b[3] = b0.w;
            b[4] = b1.x; b[5] = b1.y; b[6] = b1.z; b[7] = b1.w;
#pragma unroll
            for (int i = 0; i < TM; ++i)
#pragma unroll
                for (int j = 0; j < TN; ++j)
                    acc[i][j] = fmaf(a[i], b[j], acc[i][j]);
        }
        __syncthreads();
    }

    // epilogue: *invnorm, clip, *S. Non-label columns need no arccos/cos
    // because cos(arccos(x)) == x for x in (-1, 1).
    const int c0 = colBase + tcol * TN;
#pragma unroll
    for (int jj = 0; jj < TN; jj += 4) {
        int gc = c0 + jj;
        if (gc >= C_DIM) continue;
        float4 invn = *reinterpret_cast<const float4*>(&g_invnorm[gc]);
        float inv[4] = {invn.x, invn.y, invn.z, invn.w};
#pragma unroll
        for (int i = 0; i < TM; ++i) {
            int grow = rowBase + trow * TM + i;
            float4 o;
            float* op = reinterpret_cast<float*>(&o);
#pragma unroll
            for (int q = 0; q < 4; ++q) {
                float v = acc[i][jj + q] * inv[q];
                v = fminf(fmaxf(v, -1.0f + EPS_F), 1.0f - EPS_F);
                op[q] = v * SCALE_F;
            }
            *reinterpret_cast<float4*>(out + grow * C_DIM + gc) = o;
        }
    }
}

// ---------------------------------------------------------------------------
// Kernel 3: patch the 1024 label entries with the AdaFace margin.
// One warp per row: recompute the label-column dot product and overwrite.
// ---------------------------------------------------------------------------
__global__ void patch_label_kernel(const float* __restrict__ emb,
                                   const float* __restrict__ norms,
                                   const float* __restrict__ kern,
                                   const int*   __restrict__ label,
                                   float* __restrict__ out)
{
    int warp = (blockIdx.x * blockDim.x + threadIdx.x) >> 5;
    int lane = threadIdx.x & 31;
    if (warp >= B_DIM) return;

    int col = label[warp];
    const float* erow = emb + warp * D_DIM;

    float sum = 0.0f;
#pragma unroll
    for (int d = lane; d < D_DIM; d += 32)
        sum = fmaf(erow[d], kern[d * C_DIM + col], sum);
#pragma unroll
    for (int o = 16; o; o >>= 1)
        sum += __shfl_xor_sync(0xffffffffu, sum, o);

    if (lane == 0) {
        float cosv = sum * g_invnorm[col];
        cosv = fminf(fmaxf(cosv, -1.0f + EPS_F), 1.0f - EPS_F);

        float sn = fminf(fmaxf(norms[warp], 1e-3f), 100.0f);
        float ms = sn / (100.0f + EPS_F) * 0.333f;        // BATCH_MEAN=0
        ms = fminf(fmaxf(ms, -1.0f), 1.0f);

        float theta = acosf(cosv) + 0.5f * ms;            // M = 0.5
        const float PI_F = 3.14159265358979323846f;
        theta = fminf(fmaxf(theta, EPS_F), PI_F - EPS_F);
        float cm = cosf(theta) - (0.5f - 0.5f * ms);      // HEAD_B = 0.5
        out[warp * C_DIM + col] = cm * SCALE_F;
    }
}

// ---------------------------------------------------------------------------
extern "C" void kernel_launch(void* const* d_in, const int* in_sizes, int n_in,
                              void* d_out, int out_size)
{
    const float* emb   = (const float*)d_in[0];  // [1024, 512]
    const float* norms = (const float*)d_in[1];  // [1024, 1]
    const float* kern  = (const float*)d_in[2];  // [512, 51332]
    const int*   label = (const int*)  d_in[3];  // [1024]
    float*       out   = (float*)d_out;          // [1024, 51332]

    colnorm_kernel<<<(C_DIM + 255) / 256, 256>>>(kern);

    dim3 grid((C_DIM + BN - 1) / BN, B_DIM / BM);
    gemm_epilogue_kernel<<<grid, 256>>>(emb, kern, out);

    patch_label_kernel<<<(B_DIM * 32) / 256, 256>>>(emb, norms, kern, label, out);
}

// round 4
// speedup vs baseline: 2.5394x; 2.5394x over previous
#include <cuda_runtime.h>
#include <cuda_bf16.h>
#include <math.h>
#include <stdint.h>

#define B_DIM 1024
#define D_DIM 512
#define C_DIM 51332
#define C_PAD 51336   // padded to multiple of 8 elems -> 16B rows for cp.async

#define EPS_F   1e-3f
#define SCALE_F 64.0f

// ---------------- persistent device scratch (no runtime allocation) --------
__device__ float          g_invnorm[C_DIM];
__device__ __nv_bfloat16  g_khi[D_DIM * C_PAD];
__device__ __nv_bfloat16  g_klo[D_DIM * C_PAD];
__device__ __nv_bfloat16  g_ehi[B_DIM * D_DIM];
__device__ __nv_bfloat16  g_elo[B_DIM * D_DIM];

// ---------------------------------------------------------------------------
// Kernel 1: inverse column L2 norms of kernel [D, C]
// ---------------------------------------------------------------------------
__global__ void colnorm_kernel(const float* __restrict__ kern) {
    int c = blockIdx.x * blockDim.x + threadIdx.x;
    if (c >= C_DIM) return;
    float s0 = 0.f, s1 = 0.f, s2 = 0.f, s3 = 0.f;
#pragma unroll 4
    for (int d = 0; d < D_DIM; d += 4) {
        float v0 = kern[(d + 0) * C_DIM + c];
        float v1 = kern[(d + 1) * C_DIM + c];
        float v2 = kern[(d + 2) * C_DIM + c];
        float v3 = kern[(d + 3) * C_DIM + c];
        s0 = fmaf(v0, v0, s0);
        s1 = fmaf(v1, v1, s1);
        s2 = fmaf(v2, v2, s2);
        s3 = fmaf(v3, v3, s3);
    }
    float n = fmaxf(sqrtf(s0 + s1 + s2 + s3), 1e-5f);
    g_invnorm[c] = 1.0f / n;
}

// ---------------------------------------------------------------------------
// Kernel 2: split normalized kernel into bf16 hi/lo  (kn = k * invnorm)
// ---------------------------------------------------------------------------
__global__ void ksplit_kernel(const float* __restrict__ kern) {
    int d  = blockIdx.y;
    int c0 = (blockIdx.x * blockDim.x + threadIdx.x) * 4;
    if (c0 >= C_DIM) return;
    float4 v  = *reinterpret_cast<const float4*>(kern + (size_t)d * C_DIM + c0);
    float4 in = *reinterpret_cast<const float4*>(g_invnorm + c0);
    float f[4] = { v.x * in.x, v.y * in.y, v.z * in.z, v.w * in.w };
    __nv_bfloat16 h[4], l[4];
#pragma unroll
    for (int q = 0; q < 4; ++q) {
        h[q] = __float2bfloat16_rn(f[q]);
        l[q] = __float2bfloat16_rn(f[q] - __bfloat162float(h[q]));
    }
    __nv_bfloat162* ph = reinterpret_cast<__nv_bfloat162*>(g_khi + (size_t)d * C_PAD + c0);
    __nv_bfloat162* pl = reinterpret_cast<__nv_bfloat162*>(g_klo + (size_t)d * C_PAD + c0);
    ph[0] = __halves2bfloat162(h[0], h[1]);
    ph[1] = __halves2bfloat162(h[2], h[3]);
    pl[0] = __halves2bfloat162(l[0], l[1]);
    pl[1] = __halves2bfloat162(l[2], l[3]);
    // zero the 4 pad columns once per row (thread covering the last valid quad)
    if (c0 + 4 == C_DIM) {
        __nv_bfloat162 z = __halves2bfloat162(__float2bfloat16_rn(0.f), __float2bfloat16_rn(0.f));
        __nv_bfloat162* zh = reinterpret_cast<__nv_bfloat162*>(g_khi + (size_t)d * C_PAD + C_DIM);
        __nv_bfloat162* zl = reinterpret_cast<__nv_bfloat162*>(g_klo + (size_t)d * C_PAD + C_DIM);
        zh[0] = z; zh[1] = z; zl[0] = z; zl[1] = z;
    }
}

// ---------------------------------------------------------------------------
// Kernel 3: split embeddings into bf16 hi/lo
// ---------------------------------------------------------------------------
__global__ void esplit_kernel(const float* __restrict__ emb) {
    int i = blockIdx.x * blockDim.x + threadIdx.x;
    if (i >= B_DIM * D_DIM) return;
    float v = emb[i];
    __nv_bfloat16 h = __float2bfloat16_rn(v);
    g_ehi[i] = h;
    g_elo[i] = __float2bfloat16_rn(v - __bfloat162float(h));
}

// ---------------------------------------------------------------------------
// Kernel 4: bf16x3 tensor-core GEMM with fused clip*scale epilogue
//   acc = Ahi*Bhi + Ahi*Blo + Alo*Bhi   (fp32 accumulate, ~fp32 accuracy)
// Tile: 128(M) x 128(N) x 32(K), 256 threads, warps 2x4 (64x32 per warp)
// ---------------------------------------------------------------------------
#define BKK 32
#define AS_STRIDE 40         // 128 rows x 40 bf16 (pad: conflict-free ldmatrix)
#define BS_STRIDE 136        // 32 rows x 136 bf16
#define A_TILE (128 * AS_STRIDE)
#define B_TILE (BKK * BS_STRIDE)
#define SMEM_BYTES ((4 * A_TILE + 4 * B_TILE) * 2)

__device__ __forceinline__ unsigned sptr(const void* p) {
    return (unsigned)__cvta_generic_to_shared(p);
}
__device__ __forceinline__ void cp16(unsigned dst, const void* src) {
    asm volatile("cp.async.cg.shared.global [%0], [%1], 16;" :: "r"(dst), "l"(src));
}
__device__ __forceinline__ void cp16z(unsigned dst, const void* src, int sz) {
    asm volatile("cp.async.cg.shared.global [%0], [%1], 16, %2;" :: "r"(dst), "l"(src), "r"(sz));
}
__device__ __forceinline__ void ldsm_x4(uint32_t* r, unsigned addr) {
    asm volatile("ldmatrix.sync.aligned.m8n8.x4.shared.b16 {%0,%1,%2,%3}, [%4];"
                 : "=r"(r[0]), "=r"(r[1]), "=r"(r[2]), "=r"(r[3]) : "r"(addr));
}
__device__ __forceinline__ void ldsm_x2t(uint32_t* r, unsigned addr) {
    asm volatile("ldmatrix.sync.aligned.m8n8.x2.trans.shared.b16 {%0,%1}, [%2];"
                 : "=r"(r[0]), "=r"(r[1]) : "r"(addr));
}
__device__ __forceinline__ void mma16816(float* c, const uint32_t* a, const uint32_t* b) {
    asm volatile("mma.sync.aligned.m16n8k16.row.col.f32.bf16.bf16.f32 "
                 "{%0,%1,%2,%3}, {%4,%5,%6,%7}, {%8,%9}, {%0,%1,%2,%3};"
                 : "+f"(c[0]), "+f"(c[1]), "+f"(c[2]), "+f"(c[3])
                 : "r"(a[0]), "r"(a[1]), "r"(a[2]), "r"(a[3]), "r"(b[0]), "r"(b[1]));
}

__global__ __launch_bounds__(256, 1)
void gemm_bf16x3_kernel(float* __restrict__ out)
{
    extern __shared__ __nv_bfloat16 sm[];
    __nv_bfloat16* sAhi = sm;
    __nv_bfloat16* sAlo = sAhi + 2 * A_TILE;
    __nv_bfloat16* sBhi = sAlo + 2 * A_TILE;
    __nv_bfloat16* sBlo = sBhi + 2 * B_TILE;

    const int tid  = threadIdx.x;
    const int lane = tid & 31;
    const int warp = tid >> 5;
    const int wm   = warp >> 2;      // 0..1
    const int wn   = warp & 3;       // 0..3
    const int rowBase = blockIdx.y * 128;
    const int colBase = blockIdx.x * 128;

    float acc[4][4][4];
#pragma unroll
    for (int i = 0; i < 4; ++i)
#pragma unroll
        for (int j = 0; j < 4; ++j)
#pragma unroll
            for (int q = 0; q < 4; ++q) acc[i][j][q] = 0.0f;

    // ---- stage loader (cp.async) ----
    auto load_stage = [&](int ks, int buf) {
        const int k0 = ks * BKK;
        // A: 128 rows x 32 bf16 (4 x 16B chunks/row), hi+lo
#pragma unroll
        for (int r = 0; r < 2; ++r) {
            int t   = tid + r * 256;
            int row = t >> 2;
            int ch  = t & 3;
            size_t gidx = (size_t)(rowBase + row) * D_DIM + k0 + ch * 8;
            int soff = buf * A_TILE + row * AS_STRIDE + ch * 8;
            cp16(sptr(sAhi + soff), g_ehi + gidx);
            cp16(sptr(sAlo + soff), g_elo + gidx);
        }
        // B: 32 rows x 128 bf16 (16 x 16B chunks/row), hi+lo, col guard
#pragma unroll
        for (int r = 0; r < 2; ++r) {
            int t   = tid + r * 256;
            int row = t >> 4;
            int ch  = t & 15;
            int col = colBase + ch * 8;
            int rem = C_PAD - col;                       // elems remaining
            int sz  = rem >= 8 ? 16 : (rem > 0 ? rem * 2 : 0);
            int scol = (col < C_PAD - 8) ? col : (C_PAD - 8);   // keep src in-bounds
            size_t gidx = (size_t)(k0 + row) * C_PAD + scol;
            int soff = buf * B_TILE + row * BS_STRIDE + ch * 8;
            cp16z(sptr(sBhi + soff), g_khi + gidx, sz);
            cp16z(sptr(sBlo + soff), g_klo + gidx, sz);
        }
    };

    // ---- compute one K=32 stage ----
    auto compute_stage = [&](int buf) {
        const __nv_bfloat16* Ahi = sAhi + buf * A_TILE;
        const __nv_bfloat16* Alo = sAlo + buf * A_TILE;
        const __nv_bfloat16* Bhi = sBhi + buf * B_TILE;
        const __nv_bfloat16* Blo = sBlo + buf * B_TILE;
#pragma unroll
        for (int h = 0; h < 2; ++h) {
            const int k16 = h * 16;
            uint32_t ahi[4][4], alo[4][4], bhi[4][2], blo[4][2];
#pragma unroll
            for (int mt = 0; mt < 4; ++mt) {
                int row = wm * 64 + mt * 16 + (lane & 15);
                int kc  = k16 + (lane >> 4) * 8;
                ldsm_x4(ahi[mt], sptr(Ahi + row * AS_STRIDE + kc));
                ldsm_x4(alo[mt], sptr(Alo + row * AS_STRIDE + kc));
            }
#pragma unroll
            for (int nt = 0; nt < 4; ++nt) {
                int krow = k16 + (lane & 15);
                int nc   = wn * 32 + nt * 8;
                ldsm_x2t(bhi[nt], sptr(Bhi + krow * BS_STRIDE + nc));
                ldsm_x2t(blo[nt], sptr(Blo + krow * BS_STRIDE + nc));
            }
#pragma unroll
            for (int mt = 0; mt < 4; ++mt)
#pragma unroll
                for (int nt = 0; nt < 4; ++nt) {
                    mma16816(acc[mt][nt], ahi[mt], bhi[nt]);
                    mma16816(acc[mt][nt], ahi[mt], blo[nt]);
                    mma16816(acc[mt][nt], alo[mt], bhi[nt]);
                }
        }
    };

    // ---- pipelined mainloop: 16 stages of K=32 ----
    load_stage(0, 0);
    asm volatile("cp.async.commit_group;");
    for (int ks = 0; ks < 16; ++ks) {
        if (ks + 1 < 16) {
            load_stage(ks + 1, (ks + 1) & 1);
            asm volatile("cp.async.commit_group;");
            asm volatile("cp.async.wait_group 1;");
        } else {
            asm volatile("cp.async.wait_group 0;");
        }
        __syncthreads();
        compute_stage(ks & 1);
        __syncthreads();
    }

    // ---- epilogue: clip to (-1+eps, 1-eps), * scale ----
#pragma unroll
    for (int mt = 0; mt < 4; ++mt) {
#pragma unroll
        for (int nt = 0; nt < 4; ++nt) {
            int col = colBase + wn * 32 + nt * 8 + (lane & 3) * 2;
            if (col >= C_DIM) continue;         // col even, C even -> pair valid
#pragma unroll
            for (int rr = 0; rr < 2; ++rr) {
                int row = rowBase + wm * 64 + mt * 16 + (lane >> 2) + rr * 8;
                float2 v;
                v.x = fminf(fmaxf(acc[mt][nt][rr * 2 + 0], -1.0f + EPS_F), 1.0f - EPS_F) * SCALE_F;
                v.y = fminf(fmaxf(acc[mt][nt][rr * 2 + 1], -1.0f + EPS_F), 1.0f - EPS_F) * SCALE_F;
                *reinterpret_cast<float2*>(out + (size_t)row * C_DIM + col) = v;
            }
        }
    }
}

// ---------------------------------------------------------------------------
// Kernel 5: patch the 1024 label entries with the AdaFace margin (exact fp32)
// ---------------------------------------------------------------------------
__global__ void patch_label_kernel(const float* __restrict__ emb,
                                   const float* __restrict__ norms,
                                   const float* __restrict__ kern,
                                   const int*   __restrict__ label,
                                   float* __restrict__ out)
{
    int warp = (blockIdx.x * blockDim.x + threadIdx.x) >> 5;
    int lane = threadIdx.x & 31;
    if (warp >= B_DIM) return;

    int col = label[warp];
    const float* erow = emb + warp * D_DIM;

    float sum = 0.0f;
#pragma unroll
    for (int d = lane; d < D_DIM; d += 32)
        sum = fmaf(erow[d], kern[(size_t)d * C_DIM + col], sum);
#pragma unroll
    for (int o = 16; o; o >>= 1)
        sum += __shfl_xor_sync(0xffffffffu, sum, o);

    if (lane == 0) {
        float cosv = sum * g_invnorm[col];
        cosv = fminf(fmaxf(cosv, -1.0f + EPS_F), 1.0f - EPS_F);

        float sn = fminf(fmaxf(norms[warp], 1e-3f), 100.0f);
        float ms = sn / (100.0f + EPS_F) * 0.333f;        // BATCH_MEAN = 0
        ms = fminf(fmaxf(ms, -1.0f), 1.0f);

        float theta = acosf(cosv) + 0.5f * ms;            // M = 0.5
        const float PI_F = 3.14159265358979323846f;
        theta = fminf(fmaxf(theta, EPS_F), PI_F - EPS_F);
        float cm = cosf(theta) - (0.5f - 0.5f * ms);      // HEAD_B = 0.5
        out[(size_t)warp * C_DIM + col] = cm * SCALE_F;
    }
}

// ---------------------------------------------------------------------------
extern "C" void kernel_launch(void* const* d_in, const int* in_sizes, int n_in,
                              void* d_out, int out_size)
{
    const float* emb   = (const float*)d_in[0];  // [1024, 512]
    const float* norms = (const float*)d_in[1];  // [1024, 1]
    const float* kern  = (const float*)d_in[2];  // [512, 51332]
    const int*   label = (const int*)  d_in[3];  // [1024]
    float*       out   = (float*)d_out;          // [1024, 51332]

    cudaFuncSetAttribute(gemm_bf16x3_kernel,
                         cudaFuncAttributeMaxDynamicSharedMemorySize, SMEM_BYTES);

    colnorm_kernel<<<(C_DIM + 255) / 256, 256>>>(kern);

    dim3 sgrid((C_DIM / 4 + 255) / 256, D_DIM);
    ksplit_kernel<<<sgrid, 256>>>(kern);

    esplit_kernel<<<(B_DIM * D_DIM + 255) / 256, 256>>>(emb);

    dim3 ggrid((C_DIM + 127) / 128, B_DIM / 128);
    gemm_bf16x3_kernel<<<ggrid, 256, SMEM_BYTES>>>(out);

    patch_label_kernel<<<(B_DIM * 32) / 256, 256>>>(emb, norms, kern, label, out);
}

// round 6
// speedup vs baseline: 5.6924x; 2.2417x over previous
#include <cuda_runtime.h>
#include <cuda_fp16.h>
#include <math.h>
#include <stdint.h>

#define B_DIM 1024
#define D_DIM 512
#define C_DIM 51332
#define C_PAD 51336   // padded: 16B-aligned fp16 row chunks

#define EPS_F   1e-3f
#define SCALE_F 64.0f

// ---------------- persistent device scratch (no runtime allocation) --------
__device__ __align__(256) float  g_part[4 * C_DIM];      // partial col sumsq
__device__ __align__(256) float  g_invnorm[C_DIM];
__device__ __align__(256) __half g_kf16[D_DIM * C_PAD];  // raw kernel, fp16
__device__ __align__(256) __half g_ef16[B_DIM * D_DIM];  // embeddings, fp16

// ---------------------------------------------------------------------------
// Kernel 1: partial column sumsq (4 deterministic d-chunks for occupancy)
// ---------------------------------------------------------------------------
__global__ void colnorm_part_kernel(const float* __restrict__ kern) {
    int c = blockIdx.x * blockDim.x + threadIdx.x;
    if (c >= C_DIM) return;
    int d0 = blockIdx.y * 128;
    float s0 = 0.f, s1 = 0.f, s2 = 0.f, s3 = 0.f;
#pragma unroll 8
    for (int d = d0; d < d0 + 128; d += 4) {
        float v0 = kern[(size_t)(d + 0) * C_DIM + c];
        float v1 = kern[(size_t)(d + 1) * C_DIM + c];
        float v2 = kern[(size_t)(d + 2) * C_DIM + c];
        float v3 = kern[(size_t)(d + 3) * C_DIM + c];
        s0 = fmaf(v0, v0, s0);
        s1 = fmaf(v1, v1, s1);
        s2 = fmaf(v2, v2, s2);
        s3 = fmaf(v3, v3, s3);
    }
    g_part[blockIdx.y * C_DIM + c] = (s0 + s1) + (s2 + s3);
}

// ---------------------------------------------------------------------------
// Kernel 2: finish inverse norms (deterministic sum order)
// ---------------------------------------------------------------------------
__global__ void invnorm_kernel() {
    int c = blockIdx.x * blockDim.x + threadIdx.x;
    if (c >= C_DIM) return;
    float s = ((g_part[c] + g_part[C_DIM + c]) +
               (g_part[2 * C_DIM + c] + g_part[3 * C_DIM + c]));
    float n = fmaxf(sqrtf(s), 1e-5f);
    g_invnorm[c] = 1.0f / n;
}

// ---------------------------------------------------------------------------
// Kernel 3: raw kernel -> fp16 (no normalization; invnorm applied in epilogue)
// ---------------------------------------------------------------------------
__global__ void kf16_kernel(const float* __restrict__ kern) {
    int d  = blockIdx.y;
    int c0 = (blockIdx.x * blockDim.x + threadIdx.x) * 4;
    if (c0 >= C_DIM) return;
    float4 v = *reinterpret_cast<const float4*>(kern + (size_t)d * C_DIM + c0);
    __half2 h01 = __floats2half2_rn(v.x, v.y);
    __half2 h23 = __floats2half2_rn(v.z, v.w);
    uint2 u;
    u.x = *reinterpret_cast<uint32_t*>(&h01);
    u.y = *reinterpret_cast<uint32_t*>(&h23);
    *reinterpret_cast<uint2*>(g_kf16 + (size_t)d * C_PAD + c0) = u;
    if (c0 + 4 == C_DIM) {   // zero the 4 pad columns of this row
        uint2 z = make_uint2(0u, 0u);
        *reinterpret_cast<uint2*>(g_kf16 + (size_t)d * C_PAD + C_DIM) = z;
    }
}

// ---------------------------------------------------------------------------
// Kernel 4: embeddings -> fp16
// ---------------------------------------------------------------------------
__global__ void ef16_kernel(const float* __restrict__ emb) {
    int i = (blockIdx.x * blockDim.x + threadIdx.x) * 4;
    if (i >= B_DIM * D_DIM) return;
    float4 v = *reinterpret_cast<const float4*>(emb + i);
    __half2 h01 = __floats2half2_rn(v.x, v.y);
    __half2 h23 = __floats2half2_rn(v.z, v.w);
    uint2 u;
    u.x = *reinterpret_cast<uint32_t*>(&h01);
    u.y = *reinterpret_cast<uint32_t*>(&h23);
    *reinterpret_cast<uint2*>(g_ef16 + i) = u;
}

// ---------------------------------------------------------------------------
// Kernel 5: fp16 tensor-core GEMM, epilogue: clip(acc*invnorm)*S
// Tile 128x128x32, 256 threads, warps 2x4 (64x32 per warp), 2-stage cp.async
// ---------------------------------------------------------------------------
#define BKK 32
#define AS_STRIDE 40
#define BS_STRIDE 136
#define A_TILE (128 * AS_STRIDE)
#define B_TILE (BKK * BS_STRIDE)

__device__ __forceinline__ unsigned sptr(const void* p) {
    return (unsigned)__cvta_generic_to_shared(p);
}
__device__ __forceinline__ void cp16(unsigned dst, const void* src) {
    asm volatile("cp.async.cg.shared.global [%0], [%1], 16;" :: "r"(dst), "l"(src));
}
__device__ __forceinline__ void cp16z(unsigned dst, const void* src, int sz) {
    asm volatile("cp.async.cg.shared.global [%0], [%1], 16, %2;" :: "r"(dst), "l"(src), "r"(sz));
}
__device__ __forceinline__ void ldsm_x4(uint32_t* r, unsigned addr) {
    asm volatile("ldmatrix.sync.aligned.m8n8.x4.shared.b16 {%0,%1,%2,%3}, [%4];"
                 : "=r"(r[0]), "=r"(r[1]), "=r"(r[2]), "=r"(r[3]) : "r"(addr));
}
__device__ __forceinline__ void ldsm_x2t(uint32_t* r, unsigned addr) {
    asm volatile("ldmatrix.sync.aligned.m8n8.x2.trans.shared.b16 {%0,%1}, [%2];"
                 : "=r"(r[0]), "=r"(r[1]) : "r"(addr));
}
__device__ __forceinline__ void mma16816(float* c, const uint32_t* a, const uint32_t* b) {
    asm volatile("mma.sync.aligned.m16n8k16.row.col.f32.f16.f16.f32 "
                 "{%0,%1,%2,%3}, {%4,%5,%6,%7}, {%8,%9}, {%0,%1,%2,%3};"
                 : "+f"(c[0]), "+f"(c[1]), "+f"(c[2]), "+f"(c[3])
                 : "r"(a[0]), "r"(a[1]), "r"(a[2]), "r"(a[3]), "r"(b[0]), "r"(b[1]));
}

__global__ __launch_bounds__(256, 2)
void gemm_f16_kernel(float* __restrict__ out)
{
    __shared__ __half sA[2 * A_TILE];
    __shared__ __half sB[2 * B_TILE];

    const int tid  = threadIdx.x;
    const int lane = tid & 31;
    const int warp = tid >> 5;
    const int wm   = warp >> 2;      // 0..1
    const int wn   = warp & 3;       // 0..3
    const int rowBase = blockIdx.y * 128;
    const int colBase = blockIdx.x * 128;

    float acc[4][4][4];
#pragma unroll
    for (int i = 0; i < 4; ++i)
#pragma unroll
        for (int j = 0; j < 4; ++j)
#pragma unroll
            for (int q = 0; q < 4; ++q) acc[i][j][q] = 0.0f;

    auto load_stage = [&](int ks, int buf) {
        const int k0 = ks * BKK;
        // A: 128 rows x 32 half = 512 x 16B chunks
#pragma unroll
        for (int r = 0; r < 2; ++r) {
            int t   = tid + r * 256;
            int row = t >> 2;
            int ch  = t & 3;
            size_t gidx = (size_t)(rowBase + row) * D_DIM + k0 + ch * 8;
            cp16(sptr(sA + buf * A_TILE + row * AS_STRIDE + ch * 8), g_ef16 + gidx);
        }
        // B: 32 rows x 128 half = 512 x 16B chunks, col guard via zero-fill
#pragma unroll
        for (int r = 0; r < 2; ++r) {
            int t   = tid + r * 256;
            int row = t >> 4;
            int ch  = t & 15;
            int col = colBase + ch * 8;
            int rem = C_PAD - col;
            int sz  = rem >= 8 ? 16 : (rem > 0 ? rem * 2 : 0);
            int scol = (col < C_PAD - 8) ? col : (C_PAD - 8);
            size_t gidx = (size_t)(k0 + row) * C_PAD + scol;
            cp16z(sptr(sB + buf * B_TILE + row * BS_STRIDE + ch * 8), g_kf16 + gidx, sz);
        }
    };

    auto compute_stage = [&](int buf) {
        const __half* A = sA + buf * A_TILE;
        const __half* Bt = sB + buf * B_TILE;
#pragma unroll
        for (int h = 0; h < 2; ++h) {
            const int k16 = h * 16;
            uint32_t af[4][4], bf[4][2];
#pragma unroll
            for (int mt = 0; mt < 4; ++mt) {
                int row = wm * 64 + mt * 16 + (lane & 15);
                int kc  = k16 + (lane >> 4) * 8;
                ldsm_x4(af[mt], sptr(A + row * AS_STRIDE + kc));
            }
#pragma unroll
            for (int nt = 0; nt < 4; ++nt) {
                int krow = k16 + (lane & 15);
                int nc   = wn * 32 + nt * 8;
                ldsm_x2t(bf[nt], sptr(Bt + krow * BS_STRIDE + nc));
            }
#pragma unroll
            for (int mt = 0; mt < 4; ++mt)
#pragma unroll
                for (int nt = 0; nt < 4; ++nt)
                    mma16816(acc[mt][nt], af[mt], bf[nt]);
        }
    };

    load_stage(0, 0);
    asm volatile("cp.async.commit_group;");
    for (int ks = 0; ks < 16; ++ks) {
        if (ks + 1 < 16) {
            load_stage(ks + 1, (ks + 1) & 1);
            asm volatile("cp.async.commit_group;");
            asm volatile("cp.async.wait_group 1;");
        } else {
            asm volatile("cp.async.wait_group 0;");
        }
        __syncthreads();
        compute_stage(ks & 1);
        __syncthreads();
    }

    // epilogue: * invnorm[c], clip to (-1+eps, 1-eps), * scale
#pragma unroll
    for (int mt = 0; mt < 4; ++mt) {
#pragma unroll
        for (int nt = 0; nt < 4; ++nt) {
            int col = colBase + wn * 32 + nt * 8 + (lane & 3) * 2;
            if (col >= C_DIM) continue;   // col even, C_DIM even -> pair valid
            float2 inv = *reinterpret_cast<const float2*>(g_invnorm + col);
#pragma unroll
            for (int rr = 0; rr < 2; ++rr) {
                int row = rowBase + wm * 64 + mt * 16 + (lane >> 2) + rr * 8;
                float2 v;
                v.x = fminf(fmaxf(acc[mt][nt][rr * 2 + 0] * inv.x, -1.0f + EPS_F), 1.0f - EPS_F) * SCALE_F;
                v.y = fminf(fmaxf(acc[mt][nt][rr * 2 + 1] * inv.y, -1.0f + EPS_F), 1.0f - EPS_F) * SCALE_F;
                *reinterpret_cast<float2*>(out + (size_t)row * C_DIM + col) = v;
            }
        }
    }
}

// ---------------------------------------------------------------------------
// Kernel 6: patch the 1024 label entries with the AdaFace margin (exact fp32)
// ---------------------------------------------------------------------------
__global__ void patch_label_kernel(const float* __restrict__ emb,
                                   const float* __restrict__ norms,
                                   const float* __restrict__ kern,
                                   const int*   __restrict__ label,
                                   float* __restrict__ out)
{
    int warp = (blockIdx.x * blockDim.x + threadIdx.x) >> 5;
    int lane = threadIdx.x & 31;
    if (warp >= B_DIM) return;

    int col = label[warp];
    const float* erow = emb + (size_t)warp * D_DIM;

    float sum = 0.0f;
#pragma unroll
    for (int d = lane; d < D_DIM; d += 32)
        sum = fmaf(erow[d], kern[(size_t)d * C_DIM + col], sum);
#pragma unroll
    for (int o = 16; o; o >>= 1)
        sum += __shfl_xor_sync(0xffffffffu, sum, o);

    if (lane == 0) {
        float cosv = sum * g_invnorm[col];
        cosv = fminf(fmaxf(cosv, -1.0f + EPS_F), 1.0f - EPS_F);

        float sn = fminf(fmaxf(norms[warp], 1e-3f), 100.0f);
        float ms = sn / (100.0f + EPS_F) * 0.333f;        // BATCH_MEAN = 0
        ms = fminf(fmaxf(ms, -1.0f), 1.0f);

        float theta = acosf(cosv) + 0.5f * ms;            // M = 0.5
        const float PI_F = 3.14159265358979323846f;
        theta = fminf(fmaxf(theta, EPS_F), PI_F - EPS_F);
        float cm = cosf(theta) - (0.5f - 0.5f * ms);      // HEAD_B = 0.5
        out[(size_t)warp * C_DIM + col] = cm * SCALE_F;
    }
}

// ---------------------------------------------------------------------------
extern "C" void kernel_launch(void* const* d_in, const int* in_sizes, int n_in,
                              void* d_out, int out_size)
{
    const float* emb   = (const float*)d_in[0];  // [1024, 512]
    const float* norms = (const float*)d_in[1];  // [1024, 1]
    const float* kern  = (const float*)d_in[2];  // [512, 51332]
    const int*   label = (const int*)  d_in[3];  // [1024]
    float*       out   = (float*)d_out;          // [1024, 51332]

    dim3 cgrid((C_DIM + 255) / 256, 4);
    colnorm_part_kernel<<<cgrid, 256>>>(kern);
    invnorm_kernel<<<(C_DIM + 255) / 256, 256>>>();

    dim3 kgrid((C_DIM / 4 + 255) / 256, D_DIM);
    kf16_kernel<<<kgrid, 256>>>(kern);

    ef16_kernel<<<(B_DIM * D_DIM / 4 + 255) / 256, 256>>>(emb);

    dim3 ggrid((C_DIM + 127) / 128, B_DIM / 128);
    gemm_f16_kernel<<<ggrid, 256>>>(out);

    patch_label_kernel<<<(B_DIM * 32) / 256, 256>>>(emb, norms, kern, label, out);
}

// round 11
// speedup vs baseline: 5.7761x; 1.0147x over previous
#include <cuda_runtime.h>
#include <cuda_fp16.h>
#include <math.h>
#include <stdint.h>

#define B_DIM 1024
#define D_DIM 512
#define C_DIM 51332
#define C_TILES 402
#define C_PAD (C_TILES * 128)       // 51456: full-tile padded column count

#define EPS_F   1e-3f
#define SCALE_F 64.0f

// ---------------- persistent device scratch (no runtime allocation) --------
__device__ __align__(256) float  g_invnorm[C_DIM];
__device__ __align__(256) __half g_kf16[(size_t)D_DIM * C_PAD];  // kernel fp16 [D, C_PAD]
__device__ __align__(256) __half g_ef16[B_DIM * D_DIM];          // emb fp16 [B, D]

// ---------------------------------------------------------------------------
// Kernel 1: fused fp16-convert + column sumsq + invnorm (single pass over kern)
// ---------------------------------------------------------------------------
__global__ void kprep_kernel(const float* __restrict__ kern) {
    int c = blockIdx.x * blockDim.x + threadIdx.x;
    if (c >= C_PAD) return;
    const bool valid = (c < C_DIM);
    float s0 = 0.f, s1 = 0.f, s2 = 0.f, s3 = 0.f;
#pragma unroll 4
    for (int d = 0; d < D_DIM; d += 4) {
        float v0 = valid ? kern[(size_t)(d + 0) * C_DIM + c] : 0.0f;
        float v1 = valid ? kern[(size_t)(d + 1) * C_DIM + c] : 0.0f;
        float v2 = valid ? kern[(size_t)(d + 2) * C_DIM + c] : 0.0f;
        float v3 = valid ? kern[(size_t)(d + 3) * C_DIM + c] : 0.0f;
        s0 = fmaf(v0, v0, s0);
        s1 = fmaf(v1, v1, s1);
        s2 = fmaf(v2, v2, s2);
        s3 = fmaf(v3, v3, s3);
        g_kf16[(size_t)(d + 0) * C_PAD + c] = __float2half_rn(v0);
        g_kf16[(size_t)(d + 1) * C_PAD + c] = __float2half_rn(v1);
        g_kf16[(size_t)(d + 2) * C_PAD + c] = __float2half_rn(v2);
        g_kf16[(size_t)(d + 3) * C_PAD + c] = __float2half_rn(v3);
    }
    if (valid) {
        float n = fmaxf(sqrtf((s0 + s1) + (s2 + s3)), 1e-5f);
        g_invnorm[c] = 1.0f / n;
    }
}

// ---------------------------------------------------------------------------
// Kernel 2: embeddings -> fp16
// ---------------------------------------------------------------------------
__global__ void ef16_kernel(const float* __restrict__ emb) {
    int i = (blockIdx.x * blockDim.x + threadIdx.x) * 4;
    if (i >= B_DIM * D_DIM) return;
    float4 v = *reinterpret_cast<const float4*>(emb + i);
    __half2 h01 = __floats2half2_rn(v.x, v.y);
    __half2 h23 = __floats2half2_rn(v.z, v.w);
    uint2 u;
    u.x = *reinterpret_cast<uint32_t*>(&h01);
    u.y = *reinterpret_cast<uint32_t*>(&h23);
    *reinterpret_cast<uint2*>(g_ef16 + i) = u;
}

// ---------------------------------------------------------------------------
// Kernel 3: fp16 mma.sync GEMM (PROVEN R5 mainloop structure)
// Tile 128x128x32, 256 threads, warps 2x4 (64x32 per warp), 2-stage cp.async
// ---------------------------------------------------------------------------
#define BKK 32
#define AS_STRIDE 40
#define BS_STRIDE 136
#define A_TILE (128 * AS_STRIDE)
#define B_TILE (BKK * BS_STRIDE)

__device__ __forceinline__ unsigned sptr(const void* p) {
    return (unsigned)__cvta_generic_to_shared(p);
}
__device__ __forceinline__ void cp16(unsigned dst, const void* src) {
    asm volatile("cp.async.cg.shared.global [%0], [%1], 16;" :: "r"(dst), "l"(src));
}
__device__ __forceinline__ void ldsm_x4(uint32_t* r, unsigned addr) {
    asm volatile("ldmatrix.sync.aligned.m8n8.x4.shared.b16 {%0,%1,%2,%3}, [%4];"
                 : "=r"(r[0]), "=r"(r[1]), "=r"(r[2]), "=r"(r[3]) : "r"(addr));
}
__device__ __forceinline__ void ldsm_x2t(uint32_t* r, unsigned addr) {
    asm volatile("ldmatrix.sync.aligned.m8n8.x2.trans.shared.b16 {%0,%1}, [%2];"
                 : "=r"(r[0]), "=r"(r[1]) : "r"(addr));
}
__device__ __forceinline__ void mma16816(float* c, const uint32_t* a, const uint32_t* b) {
    asm volatile("mma.sync.aligned.m16n8k16.row.col.f32.f16.f16.f32 "
                 "{%0,%1,%2,%3}, {%4,%5,%6,%7}, {%8,%9}, {%0,%1,%2,%3};"
                 : "+f"(c[0]), "+f"(c[1]), "+f"(c[2]), "+f"(c[3])
                 : "r"(a[0]), "r"(a[1]), "r"(a[2]), "r"(a[3]), "r"(b[0]), "r"(b[1]));
}

__global__ __launch_bounds__(256, 2)
void gemm_f16_kernel(float* __restrict__ out)
{
    __shared__ __half sA[2 * A_TILE];
    __shared__ __half sB[2 * B_TILE];

    const int tid  = threadIdx.x;
    const int lane = tid & 31;
    const int warp = tid >> 5;
    const int wm   = warp >> 2;      // 0..1
    const int wn   = warp & 3;       // 0..3
    const int rowBase = blockIdx.x * 128;   // row tile fastest -> B slab L2 reuse
    const int colBase = blockIdx.y * 128;

    float acc[4][4][4];
#pragma unroll
    for (int i = 0; i < 4; ++i)
#pragma unroll
        for (int j = 0; j < 4; ++j)
#pragma unroll
            for (int q = 0; q < 4; ++q) acc[i][j][q] = 0.0f;

    auto load_stage = [&](int ks, int buf) {
        const int k0 = ks * BKK;
        // A: 128 rows x 32 half = 512 x 16B chunks
#pragma unroll
        for (int r = 0; r < 2; ++r) {
            int t   = tid + r * 256;
            int row = t >> 2;
            int ch  = t & 3;
            cp16(sptr(sA + buf * A_TILE + row * AS_STRIDE + ch * 8),
                 g_ef16 + (size_t)(rowBase + row) * D_DIM + k0 + ch * 8);
        }
        // B: 32 rows x 128 half = 512 x 16B chunks (no guard: C_PAD full tiles)
#pragma unroll
        for (int r = 0; r < 2; ++r) {
            int t   = tid + r * 256;
            int row = t >> 4;
            int ch  = t & 15;
            cp16(sptr(sB + buf * B_TILE + row * BS_STRIDE + ch * 8),
                 g_kf16 + (size_t)(k0 + row) * C_PAD + colBase + ch * 8);
        }
    };

    auto compute_stage = [&](int buf) {
        const __half* A  = sA + buf * A_TILE;
        const __half* Bt = sB + buf * B_TILE;
#pragma unroll
        for (int h = 0; h < 2; ++h) {
            const int k16 = h * 16;
            uint32_t af[4][4], bf[4][2];
#pragma unroll
            for (int mt = 0; mt < 4; ++mt) {
                int row = wm * 64 + mt * 16 + (lane & 15);
                int kc  = k16 + (lane >> 4) * 8;
                ldsm_x4(af[mt], sptr(A + row * AS_STRIDE + kc));
            }
#pragma unroll
            for (int nt = 0; nt < 4; ++nt) {
                int krow = k16 + (lane & 15);
                int nc   = wn * 32 + nt * 8;
                ldsm_x2t(bf[nt], sptr(Bt + krow * BS_STRIDE + nc));
            }
#pragma unroll
            for (int mt = 0; mt < 4; ++mt)
#pragma unroll
                for (int nt = 0; nt < 4; ++nt)
                    mma16816(acc[mt][nt], af[mt], bf[nt]);
        }
    };

    // ---- proven 2-stage pipeline: 16 stages of K=32 ----
    load_stage(0, 0);
    asm volatile("cp.async.commit_group;");
    for (int ks = 0; ks < 16; ++ks) {
        if (ks + 1 < 16) {
            load_stage(ks + 1, (ks + 1) & 1);
            asm volatile("cp.async.commit_group;");
            asm volatile("cp.async.wait_group 1;");
        } else {
            asm volatile("cp.async.wait_group 0;");
        }
        __syncthreads();
        compute_stage(ks & 1);
        __syncthreads();
    }

    // epilogue: * invnorm[c], clip, * scale  (pairs: col even, C_DIM even)
#pragma unroll
    for (int mt = 0; mt < 4; ++mt) {
#pragma unroll
        for (int nt = 0; nt < 4; ++nt) {
            int col = colBase + wn * 32 + nt * 8 + (lane & 3) * 2;
            if (col >= C_DIM) continue;
            float2 inv = *reinterpret_cast<const float2*>(g_invnorm + col);
#pragma unroll
            for (int rr = 0; rr < 2; ++rr) {
                int row = rowBase + wm * 64 + mt * 16 + (lane >> 2) + rr * 8;
                float2 v;
                v.x = fminf(fmaxf(acc[mt][nt][rr * 2 + 0] * inv.x, -1.0f + EPS_F), 1.0f - EPS_F) * SCALE_F;
                v.y = fminf(fmaxf(acc[mt][nt][rr * 2 + 1] * inv.y, -1.0f + EPS_F), 1.0f - EPS_F) * SCALE_F;
                *reinterpret_cast<float2*>(out + (size_t)row * C_DIM + col) = v;
            }
        }
    }
}

// ---------------------------------------------------------------------------
// Kernel 4: patch label entries with the AdaFace margin (exact fp32)
// ---------------------------------------------------------------------------
__global__ void patch_label_kernel(const float* __restrict__ emb,
                                   const float* __restrict__ norms,
                                   const float* __restrict__ kern,
                                   const int*   __restrict__ label,
                                   float* __restrict__ out)
{
    int warp = (blockIdx.x * blockDim.x + threadIdx.x) >> 5;
    int lane = threadIdx.x & 31;
    if (warp >= B_DIM) return;

    int col = label[warp];
    const float* erow = emb + (size_t)warp * D_DIM;

    float sum = 0.0f;
#pragma unroll
    for (int d = lane; d < D_DIM; d += 32)
        sum = fmaf(erow[d], kern[(size_t)d * C_DIM + col], sum);
#pragma unroll
    for (int o = 16; o; o >>= 1)
        sum += __shfl_xor_sync(0xffffffffu, sum, o);

    if (lane == 0) {
        float cosv = sum * g_invnorm[col];
        cosv = fminf(fmaxf(cosv, -1.0f + EPS_F), 1.0f - EPS_F);

        float sn = fminf(fmaxf(norms[warp], 1e-3f), 100.0f);
        float ms = sn / (100.0f + EPS_F) * 0.333f;        // BATCH_MEAN = 0
        ms = fminf(fmaxf(ms, -1.0f), 1.0f);

        float theta = acosf(cosv) + 0.5f * ms;            // M = 0.5
        const float PI_F = 3.14159265358979323846f;
        theta = fminf(fmaxf(theta, EPS_F), PI_F - EPS_F);
        float cm = cosf(theta) - (0.5f - 0.5f * ms);      // HEAD_B = 0.5
        out[(size_t)warp * C_DIM + col] = cm * SCALE_F;
    }
}

// ---------------------------------------------------------------------------
extern "C" void kernel_launch(void* const* d_in, const int* in_sizes, int n_in,
                              void* d_out, int out_size)
{
    const float* emb   = (const float*)d_in[0];  // [1024, 512]
    const float* norms = (const float*)d_in[1];  // [1024, 1]
    const float* kern  = (const float*)d_in[2];  // [512, 51332]
    const int*   label = (const int*)  d_in[3];  // [1024]
    float*       out   = (float*)d_out;          // [1024, 51332]

    kprep_kernel<<<C_PAD / 256, 256>>>(kern);
    ef16_kernel<<<(B_DIM * D_DIM / 4 + 255) / 256, 256>>>(emb);

    dim3 ggrid(B_DIM / 128, C_TILES);   // row tile fastest -> B slab L2 reuse
    gemm_f16_kernel<<<ggrid, 256>>>(out);

    patch_label_kernel<<<(B_DIM * 32) / 256, 256>>>(emb, norms, kern, label, out);
}